// round 12
// baseline (speedup 1.0000x reference)
#include <cuda_runtime.h>
#include <cstdint>

namespace {
constexpr int BTOT = 32768;
constexpr int T = 28;
constexpr int D = 28;
constexpr int H = 10;
constexpr int BLK = 128;   // threads per CTA
constexpr int SPB = 32;    // samples per CTA (4 lanes per sample, 1 sample/thread)

__device__ __forceinline__ float sigm(float x) {
    float e = __expf(-x);
    return __fdividef(1.0f, 1.0f + e);
}
__device__ __forceinline__ float tanh_(float x) {
    float e = __expf(2.0f * x);
    return 1.0f - __fdividef(2.0f, e + 1.0f);
}
__device__ __forceinline__ void fma2(uint64_t& d, uint64_t a, uint64_t b) {
    asm("fma.rn.f32x2 %0, %1, %2, %0;" : "+l"(d) : "l"(a), "l"(b));
}
__device__ __forceinline__ void unp2(uint64_t v, float& lo, float& hi) {
    asm("mov.b64 {%0, %1}, %2;" : "=f"(lo), "=f"(hi) : "l"(v));
}

// Gate rows 0..39 = i(0-9), f(10-19), g(20-29), o(30-39).
// Packed accumulator row j = a*2+p (a=unit 0..9): p=0 -> (i_a, f_a), p=1 -> (g_a, o_a).
// f32x2 element c: c=0 -> gate row a+p*20 ; c=1 -> row a+10+p*20.
// Lane l (0..3): p = l&1, unit group a0 = (l>>1)*5 (units a0..a0+4).

__global__ void __launch_bounds__(BLK, 7) lstm_all(
    const float* __restrict__ x,
    const float* __restrict__ w_ih0, const float* __restrict__ w_hh0,
    const float* __restrict__ b_ih0, const float* __restrict__ b_hh0,
    const float* __restrict__ w_ih1, const float* __restrict__ w_hh1,
    const float* __restrict__ b_ih1, const float* __restrict__ b_hh1,
    const float* __restrict__ w_cls, const float* __restrict__ b_cls,
    float* __restrict__ out)
{
    __shared__ __align__(16) float s_wx [20 * D * 2];   // [j][d][c]   1120 f
    __shared__ __align__(16) float s_w0h[20 * H * 2];   // [j][k][c]    400 f
    __shared__ __align__(16) float s_w1i[20 * H * 2];
    __shared__ __align__(16) float s_w1h[20 * H * 2];
    __shared__ __align__(8)  float s_b0p[40];           // [j][c]
    __shared__ __align__(8)  float s_b1p[40];
    __shared__ float s_wc[100];
    __shared__ float s_bc[10];
    __shared__ __align__(16) float s_xd[SPB * 60];      // x dup'd {v,v}; row 240B
    __shared__ __align__(16) float s_h0[SPB * 20];      // h dup'd {h,h}; row 80B
    __shared__ __align__(16) float s_h1[SPB * 20];

    const int tid = threadIdx.x;

    // ---- stage packed weights / biases; zero h buffers ----
    for (int i = tid; i < 20 * D * 2; i += BLK) {
        int c = i & 1, dd = (i >> 1) % D, j = (i >> 1) / D;
        int a = j >> 1, p = j & 1;
        s_wx[i] = w_ih0[(a + p * 20 + c * 10) * D + dd];
    }
    for (int i = tid; i < 20 * H * 2; i += BLK) {
        int c = i & 1, k = (i >> 1) % H, j = (i >> 1) / H;
        int a = j >> 1, p = j & 1;
        int row = a + p * 20 + c * 10;
        s_w0h[i] = w_hh0[row * H + k];
        s_w1i[i] = w_ih1[row * H + k];
        s_w1h[i] = w_hh1[row * H + k];
    }
    for (int i = tid; i < 40; i += BLK) {
        int c = i & 1, j = i >> 1, a = j >> 1, p = j & 1;
        int row = a + p * 20 + c * 10;
        s_b0p[i] = b_ih0[row] + b_hh0[row];
        s_b1p[i] = b_ih1[row] + b_hh1[row];
    }
    for (int i = tid; i < 100; i += BLK) s_wc[i] = w_cls[i];
    if (tid < 10) s_bc[tid] = b_cls[tid];
    for (int i = tid; i < SPB * 20; i += BLK) { s_h0[i] = 0.0f; s_h1[i] = 0.0f; }

    const int l  = tid & 3;
    const int p  = l & 1;
    const int a0 = (l >> 1) * 5;
    const int s0 = tid >> 2;          // this thread's sample (0..31)

    // unified lo-gate activation: p=0 -> sigm, p=1 -> tanh
    const float scl = p ? 2.0f : -1.0f;
    const float A_  = p ? 1.0f : 0.0f;
    const float B_  = p ? -2.0f : 1.0f;

    const float* wxl  = s_wx  + (a0 * 2 + p) * (D * 2);   // +u*112 floats, +q*4
    const float* w0l  = s_w0h + (a0 * 2 + p) * (H * 2);   // +u*40, +q*4
    const float* w1il = s_w1i + (a0 * 2 + p) * (H * 2);
    const float* w1hl = s_w1h + (a0 * 2 + p) * (H * 2);
    const float* b0l  = s_b0p + (a0 * 2 + p) * 2;         // +u*4
    const float* b1l  = s_b1p + (a0 * 2 + p) * 2;

    float c0[5], c1[5];
    #pragma unroll
    for (int u = 0; u < 5; u++) { c0[u] = 0.0f; c1[u] = 0.0f; }

    const int s_init = tid / D;
    const int d_init = tid - s_init * D;
    const float* xblk = x + (size_t)blockIdx.x * SPB * (T * D);

    #pragma unroll 1
    for (int t = 0; t < T; t++) {
        __syncthreads();
        {   // coalesced stage of x[32 samples][t][0..27], written duplicated {v,v}
            const float* src = xblk + t * D;
            int e = tid, s = s_init, d = d_init;
            #pragma unroll
            for (int k = 0; k < SPB * D / BLK; k++) {   // 7
                float v = src[e + s * (T * D - D)];
                *(float2*)(s_xd + s * 60 + 2 * d) = make_float2(v, v);
                e += BLK;
                d += (BLK - 4 * D);   // +16
                s += 4;
                if (d >= D) { d -= D; s += 1; }
            }
        }
        __syncthreads();

        uint64_t acc[5];
        #pragma unroll
        for (int u = 0; u < 5; u++)
            acc[u] = *(const uint64_t*)(b0l + 4 * u);

        // ---------- layer 0: x-projection ----------
        #pragma unroll
        for (int q = 0; q < D / 2; q++) {
            ulonglong2 xv = *(const ulonglong2*)(s_xd + s0 * 60 + q * 4);
            #pragma unroll
            for (int u = 0; u < 5; u++) {
                ulonglong2 w = *(const ulonglong2*)(wxl + u * (D * 2 * 2) + q * 4);
                fma2(acc[u], w.x, xv.x); fma2(acc[u], w.y, xv.y);
            }
        }
        // ---------- layer 0: recurrent ----------
        #pragma unroll
        for (int q = 0; q < H / 2; q++) {
            ulonglong2 hv = *(const ulonglong2*)(s_h0 + s0 * 20 + q * 4);
            #pragma unroll
            for (int u = 0; u < 5; u++) {
                ulonglong2 w = *(const ulonglong2*)(w0l + u * (H * 2 * 2) + q * 4);
                fma2(acc[u], w.x, hv.x); fma2(acc[u], w.y, hv.y);
            }
        }
        // ---------- layer 0: gates + cell ----------
        __syncwarp();   // all lanes done reading s_h0 before owner overwrites
        #pragma unroll
        for (int u = 0; u < 5; u++) {
            float lo, hi; unp2(acc[u], lo, hi);
            float loA = fmaf(B_, __fdividef(1.0f, 1.0f + __expf(scl * lo)), A_);
            float hiA = sigm(hi);
            float oLoA = __shfl_xor_sync(0xffffffffu, loA, 1);
            float oHiA = __shfl_xor_sync(0xffffffffu, hiA, 1);
            float prod = loA * oLoA;                 // sigm(i)*tanh(g), both roles
            float fv = p ? oHiA : hiA;
            float ov = p ? hiA : oHiA;
            float cn = fmaf(fv, c0[u], prod);
            c0[u] = cn;
            float ht = ov * tanh_(cn);
            if (p == 0)
                *(float2*)(s_h0 + s0 * 20 + (a0 + u) * 2) = make_float2(ht, ht);
        }
        __syncwarp();

        // ---------- layer 1 ----------
        #pragma unroll
        for (int u = 0; u < 5; u++)
            acc[u] = *(const uint64_t*)(b1l + 4 * u);
        #pragma unroll
        for (int q = 0; q < H / 2; q++) {       // input = new h0
            ulonglong2 hv = *(const ulonglong2*)(s_h0 + s0 * 20 + q * 4);
            #pragma unroll
            for (int u = 0; u < 5; u++) {
                ulonglong2 w = *(const ulonglong2*)(w1il + u * (H * 2 * 2) + q * 4);
                fma2(acc[u], w.x, hv.x); fma2(acc[u], w.y, hv.y);
            }
        }
        #pragma unroll
        for (int q = 0; q < H / 2; q++) {       // recurrent = old h1
            ulonglong2 hv = *(const ulonglong2*)(s_h1 + s0 * 20 + q * 4);
            #pragma unroll
            for (int u = 0; u < 5; u++) {
                ulonglong2 w = *(const ulonglong2*)(w1hl + u * (H * 2 * 2) + q * 4);
                fma2(acc[u], w.x, hv.x); fma2(acc[u], w.y, hv.y);
            }
        }
        __syncwarp();
        #pragma unroll
        for (int u = 0; u < 5; u++) {
            float lo, hi; unp2(acc[u], lo, hi);
            float loA = fmaf(B_, __fdividef(1.0f, 1.0f + __expf(scl * lo)), A_);
            float hiA = sigm(hi);
            float oLoA = __shfl_xor_sync(0xffffffffu, loA, 1);
            float oHiA = __shfl_xor_sync(0xffffffffu, hiA, 1);
            float prod = loA * oLoA;
            float fv = p ? oHiA : hiA;
            float ov = p ? hiA : oHiA;
            float cn = fmaf(fv, c1[u], prod);
            c1[u] = cn;
            float ht = ov * tanh_(cn);
            if (p == 0)
                *(float2*)(s_h1 + s0 * 20 + (a0 + u) * 2) = make_float2(ht, ht);
        }
        __syncwarp();
    }

    // ---------- classifier: out = h1 @ w_cls^T + b_cls ----------
    #pragma unroll
    for (int r = l; r < 10; r += 4) {
        float acc = s_bc[r];
        #pragma unroll
        for (int k = 0; k < H; k++)
            acc = fmaf(s_wc[r * 10 + k], s_h1[s0 * 20 + 2 * k], acc);
        out[((size_t)blockIdx.x * SPB + s0) * 10 + r] = acc;
    }
}
} // namespace

extern "C" void kernel_launch(void* const* d_in, const int* in_sizes, int n_in,
                              void* d_out, int out_size)
{
    (void)in_sizes; (void)n_in; (void)out_size;
    const float* x     = (const float*)d_in[0];
    const float* w_ih0 = (const float*)d_in[1];
    const float* w_hh0 = (const float*)d_in[2];
    const float* b_ih0 = (const float*)d_in[3];
    const float* b_hh0 = (const float*)d_in[4];
    const float* w_ih1 = (const float*)d_in[5];
    const float* w_hh1 = (const float*)d_in[6];
    const float* b_ih1 = (const float*)d_in[7];
    const float* b_hh1 = (const float*)d_in[8];
    const float* w_cls = (const float*)d_in[9];
    const float* b_cls = (const float*)d_in[10];

    lstm_all<<<BTOT / SPB, BLK>>>(x, w_ih0, w_hh0, b_ih0, b_hh0,
                                  w_ih1, w_hh1, b_ih1, b_hh1,
                                  w_cls, b_cls, (float*)d_out);
}

// round 13
// speedup vs baseline: 2.4579x; 2.4579x over previous
#include <cuda_runtime.h>
#include <cstdint>

namespace {
constexpr int BTOT = 32768;
constexpr int T = 28;
constexpr int D = 28;
constexpr int H = 10;
constexpr int BLK = 128;   // threads per CTA
constexpr int SPB = 64;    // samples per CTA: 4 lanes/sample x 2 samples/thread

__device__ __forceinline__ float sigm(float x) {
    float e = __expf(-x);
    return __fdividef(1.0f, 1.0f + e);
}
__device__ __forceinline__ float tanh_(float x) {
    float e = __expf(2.0f * x);
    return 1.0f - __fdividef(2.0f, e + 1.0f);
}
__device__ __forceinline__ uint64_t dup2(float v) {
    uint64_t r;
    asm("mov.b64 %0, {%1, %1};" : "=l"(r) : "f"(v));
    return r;
}
__device__ __forceinline__ void fma2(uint64_t& d, uint64_t a, uint64_t b) {
    asm("fma.rn.f32x2 %0, %1, %2, %0;" : "+l"(d) : "l"(a), "l"(b));
}
__device__ __forceinline__ void unp2(uint64_t v, float& lo, float& hi) {
    asm("mov.b64 {%0, %1}, %2;" : "=f"(lo), "=f"(hi) : "l"(v));
}

// Gate rows 0..39 = i(0-9), f(10-19), g(20-29), o(30-39).
// Packed row j = a*2+p (a = unit 0..9): f32x2 element c -> gate row a + p*20 + c*10.
//   p=0 pair = (i_a, f_a); p=1 pair = (g_a, o_a).
// Lane l = tid&3: p = l&1, unit group g = l>>1 (units g*5..g*5+4).
// h-dependent weights stored in TWO variants (k' = lane-relative k):
//   variant v: k = (k' + v*5) % 10.  Lane uses v = g, so its h vector can stay
//   in registers ordered [own-group 5, other-group 5] with compile-time indices.

__global__ void __launch_bounds__(BLK, 4) lstm_all(
    const float* __restrict__ x,
    const float* __restrict__ w_ih0, const float* __restrict__ w_hh0,
    const float* __restrict__ b_ih0, const float* __restrict__ b_hh0,
    const float* __restrict__ w_ih1, const float* __restrict__ w_hh1,
    const float* __restrict__ b_ih1, const float* __restrict__ b_hh1,
    const float* __restrict__ w_cls, const float* __restrict__ b_cls,
    float* __restrict__ out)
{
    __shared__ __align__(16) float s_wx [20 * D * 2];      // [j][d][c] 1120 f
    __shared__ __align__(16) float s_w0h[2 * 20 * H * 2];  // [v][j][k'][c] 800 f
    __shared__ __align__(16) float s_w1i[2 * 20 * H * 2];
    __shared__ __align__(16) float s_w1h[2 * 20 * H * 2];
    __shared__ __align__(8)  float s_b0p[40];              // [j][c]
    __shared__ __align__(8)  float s_b1p[40];
    __shared__ float s_wc[2 * 100];                        // [v][r][k']
    __shared__ float s_bc[10];
    __shared__ __align__(16) float s_xd[SPB * 60];         // x dup'd {v,v}; row 240B

    const int tid = threadIdx.x;

    // ---- stage packed weights / biases ----
    for (int i = tid; i < 20 * D * 2; i += BLK) {
        int c = i & 1, dd = (i >> 1) % D, j = (i >> 1) / D;
        int a = j >> 1, p = j & 1;
        s_wx[i] = w_ih0[(a + p * 20 + c * 10) * D + dd];
    }
    for (int i = tid; i < 2 * 20 * H * 2; i += BLK) {
        int c = i & 1, kp = (i >> 1) % H, j = ((i >> 1) / H) % 20, v = (i >> 1) / (H * 20);
        int a = j >> 1, p = j & 1;
        int k = kp + v * 5; if (k >= H) k -= H;
        int row = a + p * 20 + c * 10;
        s_w0h[i] = w_hh0[row * H + k];
        s_w1i[i] = w_ih1[row * H + k];
        s_w1h[i] = w_hh1[row * H + k];
    }
    for (int i = tid; i < 40; i += BLK) {
        int c = i & 1, j = i >> 1, a = j >> 1, p = j & 1;
        int row = a + p * 20 + c * 10;
        s_b0p[i] = b_ih0[row] + b_hh0[row];
        s_b1p[i] = b_ih1[row] + b_hh1[row];
    }
    for (int i = tid; i < 200; i += BLK) {
        int v = i / 100, r = (i % 100) / 10, kp = i % 10;
        int k = kp + v * 5; if (k >= H) k -= H;
        s_wc[i] = w_cls[r * H + k];
    }
    if (tid < 10) s_bc[tid] = b_cls[tid];

    const int l = tid & 3;
    const int p = l & 1;
    const int g = l >> 1;
    const int a0 = g * 5;
    const int s0 = tid >> 2;          // sample 0 (0..31); sample 1 = s0+32

    // unified lo-gate activation: p=0 -> sigm(i), p=1 -> tanh(g)
    const float scl = p ? 2.0f : -1.0f;
    const float A_  = p ? 1.0f : 0.0f;
    const float B_  = p ? -2.0f : 1.0f;

    const float* wxl  = s_wx  + (a0 * 2 + p) * (D * 2);              // +u*112, +q*4
    const float* w0l  = s_w0h + g * 400 + (a0 * 2 + p) * (H * 2);    // +u*40, +q*4
    const float* w1il = s_w1i + g * 400 + (a0 * 2 + p) * (H * 2);
    const float* w1hl = s_w1h + g * 400 + (a0 * 2 + p) * (H * 2);
    const float* b0l  = s_b0p + (a0 * 2 + p) * 2;                    // +u*4
    const float* b1l  = s_b1p + (a0 * 2 + p) * 2;

    // lane-relative state: [sample][k']  k'=0..4 own group, 5..9 other group
    float h0r[2][10], h1r[2][10], c0[2][5], c1[2][5];
    #pragma unroll
    for (int sm = 0; sm < 2; sm++) {
        #pragma unroll
        for (int k = 0; k < 10; k++) { h0r[sm][k] = 0.0f; h1r[sm][k] = 0.0f; }
        #pragma unroll
        for (int u = 0; u < 5; u++) { c0[sm][u] = 0.0f; c1[sm][u] = 0.0f; }
    }

    const int s_init = tid / D;
    const int d_init = tid - s_init * D;
    const float* xblk = x + (size_t)blockIdx.x * SPB * (T * D);

    __syncthreads();

    #pragma unroll 1
    for (int t = 0; t < T; t++) {
        __syncthreads();
        {   // coalesced stage of x[64 samples][t][0..27], written duplicated {v,v}
            const float* src = xblk + t * D;
            int e = tid, s = s_init, d = d_init;
            #pragma unroll
            for (int k = 0; k < SPB * D / BLK; k++) {   // 14
                float v = src[e + s * (T * D - D)];
                *(float2*)(s_xd + s * 60 + 2 * d) = make_float2(v, v);
                e += BLK;
                d += (BLK - 4 * D);   // +16
                s += 4;
                if (d >= D) { d -= D; s += 1; }
            }
        }
        __syncthreads();

        uint64_t acc[2][5];
        #pragma unroll
        for (int u = 0; u < 5; u++) {
            uint64_t b = *(const uint64_t*)(b0l + 4 * u);
            acc[0][u] = b; acc[1][u] = b;
        }

        // ---------- layer 0: x-projection (weights shared by both samples) ----------
        #pragma unroll
        for (int q = 0; q < D / 2; q++) {
            ulonglong2 xv0 = *(const ulonglong2*)(s_xd + s0 * 60 + q * 4);
            ulonglong2 xv1 = *(const ulonglong2*)(s_xd + (s0 + 32) * 60 + q * 4);
            #pragma unroll
            for (int u = 0; u < 5; u++) {
                ulonglong2 w = *(const ulonglong2*)(wxl + u * (D * 2 * 2) + q * 4);
                fma2(acc[0][u], w.x, xv0.x); fma2(acc[0][u], w.y, xv0.y);
                fma2(acc[1][u], w.x, xv1.x); fma2(acc[1][u], w.y, xv1.y);
            }
        }
        // ---------- layer 0: recurrent (h in regs, dup on the fly) ----------
        #pragma unroll
        for (int q = 0; q < H / 2; q++) {
            uint64_t a0d = dup2(h0r[0][2 * q]),     a1d = dup2(h0r[0][2 * q + 1]);
            uint64_t b0d = dup2(h0r[1][2 * q]),     b1d = dup2(h0r[1][2 * q + 1]);
            #pragma unroll
            for (int u = 0; u < 5; u++) {
                ulonglong2 w = *(const ulonglong2*)(w0l + u * (H * 2 * 2) + q * 4);
                fma2(acc[0][u], w.x, a0d); fma2(acc[0][u], w.y, a1d);
                fma2(acc[1][u], w.x, b0d); fma2(acc[1][u], w.y, b1d);
            }
        }
        // ---------- layer 0: gates + cell + h exchange (shfl only) ----------
        #pragma unroll
        for (int sm = 0; sm < 2; sm++) {
            #pragma unroll
            for (int u = 0; u < 5; u++) {
                float lo, hi; unp2(acc[sm][u], lo, hi);
                float loA = fmaf(B_, __fdividef(1.0f, 1.0f + __expf(scl * lo)), A_);
                float hiA = sigm(hi);
                float oLo = __shfl_xor_sync(0xffffffffu, loA, 1);
                float oHi = __shfl_xor_sync(0xffffffffu, hiA, 1);
                float prod = loA * oLo;                 // sigm(i)*tanh(g)
                float fv = p ? oHi : hiA;
                float ov = p ? hiA : oHi;
                float cn = fmaf(fv, c0[sm][u], prod);
                c0[sm][u] = cn;
                float ht = ov * tanh_(cn);              // both p lanes identical
                float hoth = __shfl_xor_sync(0xffffffffu, ht, 2);
                h0r[sm][u] = ht;
                h0r[sm][5 + u] = hoth;
            }
        }

        // ---------- layer 1 ----------
        #pragma unroll
        for (int u = 0; u < 5; u++) {
            uint64_t b = *(const uint64_t*)(b1l + 4 * u);
            acc[0][u] = b; acc[1][u] = b;
        }
        #pragma unroll
        for (int q = 0; q < H / 2; q++) {       // input = new h0
            uint64_t a0d = dup2(h0r[0][2 * q]),     a1d = dup2(h0r[0][2 * q + 1]);
            uint64_t b0d = dup2(h0r[1][2 * q]),     b1d = dup2(h0r[1][2 * q + 1]);
            #pragma unroll
            for (int u = 0; u < 5; u++) {
                ulonglong2 w = *(const ulonglong2*)(w1il + u * (H * 2 * 2) + q * 4);
                fma2(acc[0][u], w.x, a0d); fma2(acc[0][u], w.y, a1d);
                fma2(acc[1][u], w.x, b0d); fma2(acc[1][u], w.y, b1d);
            }
        }
        #pragma unroll
        for (int q = 0; q < H / 2; q++) {       // recurrent = old h1
            uint64_t a0d = dup2(h1r[0][2 * q]),     a1d = dup2(h1r[0][2 * q + 1]);
            uint64_t b0d = dup2(h1r[1][2 * q]),     b1d = dup2(h1r[1][2 * q + 1]);
            #pragma unroll
            for (int u = 0; u < 5; u++) {
                ulonglong2 w = *(const ulonglong2*)(w1hl + u * (H * 2 * 2) + q * 4);
                fma2(acc[0][u], w.x, a0d); fma2(acc[0][u], w.y, a1d);
                fma2(acc[1][u], w.x, b0d); fma2(acc[1][u], w.y, b1d);
            }
        }
        #pragma unroll
        for (int sm = 0; sm < 2; sm++) {
            #pragma unroll
            for (int u = 0; u < 5; u++) {
                float lo, hi; unp2(acc[sm][u], lo, hi);
                float loA = fmaf(B_, __fdividef(1.0f, 1.0f + __expf(scl * lo)), A_);
                float hiA = sigm(hi);
                float oLo = __shfl_xor_sync(0xffffffffu, loA, 1);
                float oHi = __shfl_xor_sync(0xffffffffu, hiA, 1);
                float prod = loA * oLo;
                float fv = p ? oHi : hiA;
                float ov = p ? hiA : oHi;
                float cn = fmaf(fv, c1[sm][u], prod);
                c1[sm][u] = cn;
                float ht = ov * tanh_(cn);
                float hoth = __shfl_xor_sync(0xffffffffu, ht, 2);
                h1r[sm][u] = ht;
                h1r[sm][5 + u] = hoth;
            }
        }
    }

    // ---------- classifier: out = h1 @ w_cls^T + b_cls (lane-relative k') ----------
    const float* wcl = s_wc + g * 100;
    #pragma unroll
    for (int r = l; r < 10; r += 4) {
        #pragma unroll
        for (int sm = 0; sm < 2; sm++) {
            float acc = s_bc[r];
            #pragma unroll
            for (int k = 0; k < H; k++)
                acc = fmaf(wcl[r * 10 + k], h1r[sm][k], acc);
            out[((size_t)blockIdx.x * SPB + s0 + sm * 32) * 10 + r] = acc;
        }
    }
}
} // namespace

extern "C" void kernel_launch(void* const* d_in, const int* in_sizes, int n_in,
                              void* d_out, int out_size)
{
    (void)in_sizes; (void)n_in; (void)out_size;
    const float* x     = (const float*)d_in[0];
    const float* w_ih0 = (const float*)d_in[1];
    const float* w_hh0 = (const float*)d_in[2];
    const float* b_ih0 = (const float*)d_in[3];
    const float* b_hh0 = (const float*)d_in[4];
    const float* w_ih1 = (const float*)d_in[5];
    const float* w_hh1 = (const float*)d_in[6];
    const float* b_ih1 = (const float*)d_in[7];
    const float* b_hh1 = (const float*)d_in[8];
    const float* w_cls = (const float*)d_in[9];
    const float* b_cls = (const float*)d_in[10];

    lstm_all<<<BTOT / SPB, BLK>>>(x, w_ih0, w_hh0, b_ih0, b_hh0,
                                  w_ih1, w_hh1, b_ih1, b_hh1,
                                  w_cls, b_cls, (float*)d_out);
}

// round 16
// speedup vs baseline: 2.7062x; 1.1010x over previous
#include <cuda_runtime.h>
#include <cstdint>

namespace {
constexpr int BTOT = 32768;
constexpr int T = 28;
constexpr int D = 28;
constexpr int H = 10;
constexpr int BLK = 128;   // threads per CTA
constexpr int SPB = 64;    // samples per CTA: 2 lanes per sample, 1 sample/thread

__device__ __forceinline__ float sigm(float x) {
    float e = __expf(-x);
    return __fdividef(1.0f, 1.0f + e);
}
__device__ __forceinline__ float tanh_(float x) {
    float e = __expf(2.0f * x);
    return 1.0f - __fdividef(2.0f, e + 1.0f);
}
__device__ __forceinline__ uint64_t dup2(float v) {
    uint64_t r;
    asm("mov.b64 %0, {%1, %1};" : "=l"(r) : "f"(v));
    return r;
}
__device__ __forceinline__ void fma2(uint64_t& d, uint64_t a, uint64_t b) {
    asm("fma.rn.f32x2 %0, %1, %2, %0;" : "+l"(d) : "l"(a), "l"(b));
}
__device__ __forceinline__ void unp2(uint64_t v, float& lo, float& hi) {
    asm("mov.b64 {%0, %1}, %2;" : "=f"(lo), "=f"(hi) : "l"(v));
}

// Gate rows 0..39 = i(0-9), f(10-19), g(20-29), o(30-39).
// Packed row j = a*2+p (a = unit 0..9): f32x2 element c -> gate row a + p*20 + c*10.
//   p=0 pair = (i_a, f_a);  p=1 pair = (g_a, o_a).
// Lane l = tid&1 owns units A..A+4 (A=l*5) -> ALL four gates locally (acc[5][2]),
// so the cell update needs NO gate shfls; only 5 h-broadcast shfls per layer.
// Recurrent weights & classifier stored in TWO rotated variants so h can stay in
// lane-relative register order h[k'] = h[(A+k') mod 10] with compile-time indices.

__global__ void __launch_bounds__(BLK, 4) lstm_all(
    const float* __restrict__ x,
    const float* __restrict__ w_ih0, const float* __restrict__ w_hh0,
    const float* __restrict__ b_ih0, const float* __restrict__ b_hh0,
    const float* __restrict__ w_ih1, const float* __restrict__ w_hh1,
    const float* __restrict__ b_ih1, const float* __restrict__ b_hh1,
    const float* __restrict__ w_cls, const float* __restrict__ b_cls,
    float* __restrict__ out)
{
    __shared__ __align__(16) float s_wx [20 * D * 2];        // [j][d][c] 1120 f
    __shared__ __align__(16) float s_w0h[2 * 10 * H * 2];    // [v][jl][k'][c] 400 f
    __shared__ __align__(16) float s_w1i[2 * 10 * H * 2];
    __shared__ __align__(16) float s_w1h[2 * 10 * H * 2];
    __shared__ __align__(8)  float s_b0p[40];                // [j][c]
    __shared__ __align__(8)  float s_b1p[40];
    __shared__ float s_wc[2 * 100];                          // [v][r][k']
    __shared__ float s_bc[10];
    __shared__ __align__(16) float s_xd[SPB * 60];           // x dup'd {v,v}; row 240B

    const int tid = threadIdx.x;

    // ---- stage packed weights / biases ----
    for (int i = tid; i < 20 * D * 2; i += BLK) {
        int c = i & 1, dd = (i >> 1) % D, j = (i >> 1) / D;
        int a = j >> 1, p = j & 1;
        s_wx[i] = w_ih0[(a + p * 20 + c * 10) * D + dd];
    }
    // rec mats: [v][jl][k'][c], jl = u*2+p (u local), a = v*5+u, k = (k'+v*5)%10
    for (int i = tid; i < 2 * 10 * H * 2; i += BLK) {
        int c = i & 1, kp = (i >> 1) % H, jl = ((i >> 1) / H) % 10, v = (i >> 1) / (H * 10);
        int u = jl >> 1, p = jl & 1;
        int a = v * 5 + u;
        int k = kp + v * 5; if (k >= H) k -= H;
        int row = a + p * 20 + c * 10;
        s_w0h[i] = w_hh0[row * H + k];
        s_w1i[i] = w_ih1[row * H + k];
        s_w1h[i] = w_hh1[row * H + k];
    }
    for (int i = tid; i < 40; i += BLK) {
        int c = i & 1, j = i >> 1, a = j >> 1, p = j & 1;
        int row = a + p * 20 + c * 10;
        s_b0p[i] = b_ih0[row] + b_hh0[row];
        s_b1p[i] = b_ih1[row] + b_hh1[row];
    }
    for (int i = tid; i < 200; i += BLK) {
        int v = i / 100, r = (i % 100) / 10, kp = i % 10;
        int k = kp + v * 5; if (k >= H) k -= H;
        s_wc[i] = w_cls[r * H + k];
    }
    if (tid < 10) s_bc[tid] = b_cls[tid];

    const int l = tid & 1;            // lane: owns units l*5 .. l*5+4 (all 4 gates)
    const int r = tid >> 1;           // sample-in-CTA (0..63)

    const float* wxl  = s_wx  + l * 560;   // + (u*2+p)*56 + q*4
    const float* w0l  = s_w0h + l * 200;   // + (u*2+p)*20 + q*4
    const float* w1il = s_w1i + l * 200;
    const float* w1hl = s_w1h + l * 200;
    const float* b0l  = s_b0p + l * 20;    // + (u*2+p)*2
    const float* b1l  = s_b1p + l * 20;

    // lane-relative state: h[k'] = h[(l*5 + k') mod 10]; k' 0..4 own, 5..9 other
    float h0r[10], h1r[10], c0[5], c1[5];
    #pragma unroll
    for (int k = 0; k < 10; k++) { h0r[k] = 0.0f; h1r[k] = 0.0f; }
    #pragma unroll
    for (int u = 0; u < 5; u++) { c0[u] = 0.0f; c1[u] = 0.0f; }

    const int s_init = tid / D;
    const int d_init = tid - s_init * D;
    const float* xblk = x + (size_t)blockIdx.x * SPB * (T * D);

    __syncthreads();

    #pragma unroll 1
    for (int t = 0; t < T; t++) {
        __syncthreads();
        {   // coalesced stage of x[64 samples][t][0..27], written duplicated {v,v}
            const float* src = xblk + t * D;
            int e = tid, s = s_init, d = d_init;
            #pragma unroll
            for (int k = 0; k < SPB * D / BLK; k++) {   // 14
                float v = src[e + s * (T * D - D)];
                *(float2*)(s_xd + s * 60 + 2 * d) = make_float2(v, v);
                e += BLK;
                d += (BLK - 4 * D);   // +16
                s += 4;
                if (d >= D) { d -= D; s += 1; }
            }
        }
        __syncthreads();

        // ---------- layer 0 ----------
        uint64_t acc[5][2];
        #pragma unroll
        for (int u = 0; u < 5; u++) {
            acc[u][0] = *(const uint64_t*)(b0l + (u * 2 + 0) * 2);
            acc[u][1] = *(const uint64_t*)(b0l + (u * 2 + 1) * 2);
        }
        // x-projection: xv read per-q (pre-duplicated), weights per (u,p)
        #pragma unroll
        for (int q = 0; q < D / 2; q++) {
            ulonglong2 xv = *(const ulonglong2*)(s_xd + r * 60 + q * 4);
            #pragma unroll
            for (int u = 0; u < 5; u++) {
                #pragma unroll
                for (int p = 0; p < 2; p++) {
                    ulonglong2 w = *(const ulonglong2*)(wxl + (u * 2 + p) * 56 + q * 4);
                    fma2(acc[u][p], w.x, xv.x);
                    fma2(acc[u][p], w.y, xv.y);
                }
            }
        }
        // recurrent (h in regs, dup on the fly; K=10 exact)
        #pragma unroll
        for (int q = 0; q < H / 2; q++) {
            uint64_t h0d = dup2(h0r[2 * q]), h1d = dup2(h0r[2 * q + 1]);
            #pragma unroll
            for (int u = 0; u < 5; u++) {
                #pragma unroll
                for (int p = 0; p < 2; p++) {
                    ulonglong2 w = *(const ulonglong2*)(w0l + (u * 2 + p) * 20 + q * 4);
                    fma2(acc[u][p], w.x, h0d);
                    fma2(acc[u][p], w.y, h1d);
                }
            }
        }
        // gates + cell (all local) + h broadcast (1 shfl per unit)
        #pragma unroll
        for (int u = 0; u < 5; u++) {
            float iv, fv, gv, ov;
            unp2(acc[u][0], iv, fv);
            unp2(acc[u][1], gv, ov);
            iv = sigm(iv); fv = sigm(fv); gv = tanh_(gv); ov = sigm(ov);
            float cn = fmaf(fv, c0[u], iv * gv);
            c0[u] = cn;
            float ht = ov * tanh_(cn);
            float hoth = __shfl_xor_sync(0xffffffffu, ht, 1);
            h0r[u] = ht;
            h0r[5 + u] = hoth;
        }

        // ---------- layer 1 ----------
        #pragma unroll
        for (int u = 0; u < 5; u++) {
            acc[u][0] = *(const uint64_t*)(b1l + (u * 2 + 0) * 2);
            acc[u][1] = *(const uint64_t*)(b1l + (u * 2 + 1) * 2);
        }
        #pragma unroll
        for (int q = 0; q < H / 2; q++) {       // input = new h0
            uint64_t h0d = dup2(h0r[2 * q]), h1d = dup2(h0r[2 * q + 1]);
            #pragma unroll
            for (int u = 0; u < 5; u++) {
                #pragma unroll
                for (int p = 0; p < 2; p++) {
                    ulonglong2 w = *(const ulonglong2*)(w1il + (u * 2 + p) * 20 + q * 4);
                    fma2(acc[u][p], w.x, h0d);
                    fma2(acc[u][p], w.y, h1d);
                }
            }
        }
        #pragma unroll
        for (int q = 0; q < H / 2; q++) {       // recurrent = old h1
            uint64_t h0d = dup2(h1r[2 * q]), h1d = dup2(h1r[2 * q + 1]);
            #pragma unroll
            for (int u = 0; u < 5; u++) {
                #pragma unroll
                for (int p = 0; p < 2; p++) {
                    ulonglong2 w = *(const ulonglong2*)(w1hl + (u * 2 + p) * 20 + q * 4);
                    fma2(acc[u][p], w.x, h0d);
                    fma2(acc[u][p], w.y, h1d);
                }
            }
        }
        #pragma unroll
        for (int u = 0; u < 5; u++) {
            float iv, fv, gv, ov;
            unp2(acc[u][0], iv, fv);
            unp2(acc[u][1], gv, ov);
            iv = sigm(iv); fv = sigm(fv); gv = tanh_(gv); ov = sigm(ov);
            float cn = fmaf(fv, c1[u], iv * gv);
            c1[u] = cn;
            float ht = ov * tanh_(cn);
            float hoth = __shfl_xor_sync(0xffffffffu, ht, 1);
            h1r[u] = ht;
            h1r[5 + u] = hoth;
        }
    }

    // ---------- classifier: out = h1 @ w_cls^T + b_cls (lane-relative k') ----------
    const float* wcl = s_wc + l * 100;
    #pragma unroll
    for (int rr = l; rr < 10; rr += 2) {
        float acc = s_bc[rr];
        #pragma unroll
        for (int k = 0; k < H; k++)
            acc = fmaf(wcl[rr * 10 + k], h1r[k], acc);
        out[((size_t)blockIdx.x * SPB + r) * 10 + rr] = acc;
    }
}
} // namespace

extern "C" void kernel_launch(void* const* d_in, const int* in_sizes, int n_in,
                              void* d_out, int out_size)
{
    (void)in_sizes; (void)n_in; (void)out_size;
    const float* x     = (const float*)d_in[0];
    const float* w_ih0 = (const float*)d_in[1];
    const float* w_hh0 = (const float*)d_in[2];
    const float* b_ih0 = (const float*)d_in[3];
    const float* b_hh0 = (const float*)d_in[4];
    const float* w_ih1 = (const float*)d_in[5];
    const float* w_hh1 = (const float*)d_in[6];
    const float* b_ih1 = (const float*)d_in[7];
    const float* b_hh1 = (const float*)d_in[8];
    const float* w_cls = (const float*)d_in[9];
    const float* b_cls = (const float*)d_in[10];

    lstm_all<<<BTOT / SPB, BLK>>>(x, w_ih0, w_hh0, b_ih0, b_hh0,
                                  w_ih1, w_hh1, b_ih1, b_hh1,
                                  w_cls, b_cls, (float*)d_out);
}